// round 6
// baseline (speedup 1.0000x reference)
#include <cuda_runtime.h>

#define NPTS   300000
#define NPAIRS 100000
#define KOFF   27
#define CIN    32
#define COUT   64
#define NGRP   8

// ---- scratch (no allocations allowed) ----
__device__ float g_sum[NGRP];
__device__ float g_sq[NGRP];
__device__ float g_mean[NGRP];
__device__ float g_inv[NGRP];
__device__ int   g_is64;

// ---- packed fp32x2 helpers (sm_100+) ----
__device__ __forceinline__ unsigned long long pack2(float lo, float hi) {
    unsigned long long r;
    asm("mov.b64 %0, {%1, %2};" : "=l"(r) : "f"(lo), "f"(hi));
    return r;
}
__device__ __forceinline__ float hadd2(unsigned long long v) {
    float lo, hi;
    asm("mov.b64 {%0, %1}, %2;" : "=f"(lo), "=f"(hi) : "l"(v));
    return lo + hi;
}
#define FMA2(acc, b, w) \
    asm("fma.rn.f32x2 %0, %1, %2, %0;" : "+l"(acc) : "l"(b), "l"(w))

__device__ __forceinline__ void red_add_v4(float* addr, float x, float y, float z, float w) {
    asm volatile("red.global.add.v4.f32 [%0], {%1, %2, %3, %4};"
                 :: "l"(addr), "f"(x), "f"(y), "f"(z), "f"(w) : "memory");
}

// Detect whether index arrays are int64 or int32 (jax x64 flag ambiguity).
// If int64, every high 32-bit word of the first 4K entries is 0.
__global__ void detect_kernel(const unsigned int* __restrict__ idx32) {
    __shared__ int s_any;
    if (threadIdx.x == 0) s_any = 0;
    __syncthreads();
    unsigned int v = 0;
    for (int i = threadIdx.x; i < 2048; i += blockDim.x)
        v |= idx32[2 * i + 1];
    if (v) atomicOr(&s_any, 1);
    __syncthreads();
    if (threadIdx.x == 0) g_is64 = (s_any == 0) ? 1 : 0;
}

__global__ void zero_kernel(float4* __restrict__ out, int n4) {
    int i = blockIdx.x * blockDim.x + threadIdx.x;
    if (i < n4) out[i] = make_float4(0.f, 0.f, 0.f, 0.f);
    if (blockIdx.x == 0 && threadIdx.x < NGRP) {
        g_sum[threadIdx.x] = 0.f;
        g_sq[threadIdx.x]  = 0.f;
    }
}

__device__ __forceinline__ int load_idx(const void* p, long long pos, int is64) {
    if (is64) return (int)((const long long*)p)[pos];
    return ((const int*)p)[pos];
}

// Sparse conv: one warp per batch of 32 pairs. Lane l accumulates output
// channels (2l, 2l+1) via f32x2 FMAs (.lo = even cin, .hi = odd cin).
// After the horizontal add, lane pairs (2m, 2m+1) exchange via shfl.xor(1)
// and the even lane issues ONE red.global.add.v4.f32 covering channels
// 4m..4m+3 — 16 RED lane-ops per pair instead of 32.
__global__ __launch_bounds__(256, 2)
void conv_kernel(const float* __restrict__ feats,
                 const float* __restrict__ weight,
                 const void*  __restrict__ in_idx,
                 const void*  __restrict__ out_idx,
                 float*       __restrict__ out) {
    const int k    = blockIdx.y;
    const int lane = threadIdx.x & 31;
    const int warp = threadIdx.x >> 5;

    __shared__ float ws[CIN * COUT];
    const float* wk = weight + (long long)k * CIN * COUT;
    for (int i = threadIdx.x; i < CIN * COUT; i += blockDim.x) ws[i] = wk[i];
    __syncthreads();

    // wp0[c2] = (W[2c2][2l], W[2c2+1][2l]) ; wp1 same for channel 2l+1
    unsigned long long wp0[16], wp1[16];
#pragma unroll
    for (int c2 = 0; c2 < 16; c2++) {
        wp0[c2] = pack2(ws[(2*c2) * COUT + 2*lane],     ws[(2*c2+1) * COUT + 2*lane]);
        wp1[c2] = pack2(ws[(2*c2) * COUT + 2*lane + 1], ws[(2*c2+1) * COUT + 2*lane + 1]);
    }

    const int is64 = g_is64;
    const long long base = (long long)k * NPAIRS;
    const int p0 = (blockIdx.x * 8 + warp) * 32;
    if (p0 >= NPAIRS) return;

    const int p = p0 + lane;
    int ir = 0, orow = 0;
    if (p < NPAIRS) {
        ir   = load_idx(in_idx,  base + p, is64);
        orow = load_idx(out_idx, base + p, is64);
    }
    const int nv = min(32, NPAIRS - p0);
    const bool is_even = !(lane & 1);
    const int  ch4     = (lane >> 1) * 4;   // even lane's v4 channel base

    for (int j = 0; j < nv; j++) {
        const int irow = __shfl_sync(0xffffffffu, ir,   j);
        const int ro   = __shfl_sync(0xffffffffu, orow, j);
        const ulonglong2* f2 = (const ulonglong2*)(feats + (long long)irow * CIN);
        unsigned long long a0 = 0ull, a1 = 0ull;  // bits of (0.f, 0.f)
#pragma unroll
        for (int q = 0; q < 8; q++) {
            ulonglong2 fv = __ldg(f2 + q);          // broadcast, 4 floats = 2 pairs
            FMA2(a0, fv.x, wp0[2*q]);   FMA2(a1, fv.x, wp1[2*q]);
            FMA2(a0, fv.y, wp0[2*q+1]); FMA2(a1, fv.y, wp1[2*q+1]);
        }
        float v0 = hadd2(a0);                       // channel 2*lane
        float v1 = hadd2(a1);                       // channel 2*lane+1
        float o0 = __shfl_xor_sync(0xffffffffu, v0, 1);
        float o1 = __shfl_xor_sync(0xffffffffu, v1, 1);
        if (is_even)
            red_add_v4(out + (long long)ro * COUT + ch4, v0, v1, o0, o1);
    }
}

// GroupNorm stats: float4 loads; 4 channels per thread all lie in one group
// (group = c4>>1). Two butterfly shuffles fold warp partials per group.
__global__ void stats_kernel(const float4* __restrict__ out) {
    const int c4   = threadIdx.x & 15;   // float4 column 0..15
    const int ty   = threadIdx.x >> 4;   // row phase 0..15
    const int lane = threadIdx.x & 31;
    __shared__ float s_sum[NGRP], s_sq[NGRP];
    if (threadIdx.x < NGRP) { s_sum[threadIdx.x] = 0.f; s_sq[threadIdx.x] = 0.f; }
    __syncthreads();

    float sum = 0.f, sq = 0.f;
#pragma unroll 4
    for (int row = blockIdx.x * 16 + ty; row < NPTS; row += gridDim.x * 16) {
        float4 v = __ldg(out + row * 16 + c4);
        sum += (v.x + v.y) + (v.z + v.w);
        sq   = fmaf(v.x, v.x, fmaf(v.y, v.y, fmaf(v.z, v.z, fmaf(v.w, v.w, sq))));
    }
    // lanes {2g, 2g+1, 2g+16, 2g+17} share group g
    sum += __shfl_xor_sync(0xffffffffu, sum, 16);
    sq  += __shfl_xor_sync(0xffffffffu, sq,  16);
    sum += __shfl_xor_sync(0xffffffffu, sum, 1);
    sq  += __shfl_xor_sync(0xffffffffu, sq,  1);
    if (lane < 16 && !(lane & 1)) {
        atomicAdd(&s_sum[lane >> 1], sum);
        atomicAdd(&s_sq[lane >> 1],  sq);
    }
    __syncthreads();
    if (threadIdx.x < NGRP) {
        atomicAdd(&g_sum[threadIdx.x], s_sum[threadIdx.x]);
        atomicAdd(&g_sq[threadIdx.x],  s_sq[threadIdx.x]);
    }
}

__global__ void finalize_kernel() {
    int g = threadIdx.x;
    if (g < NGRP) {
        const float cnt = (float)NPTS * (COUT / NGRP);
        float m   = g_sum[g] / cnt;
        float var = g_sq[g] / cnt - m * m;
        g_mean[g] = m;
        g_inv[g]  = rsqrtf(var + 1e-5f);
    }
}

// Fused affine + LeakyReLU, float4 in/out: y = x*(inv*gamma) + (beta - m*inv*gamma)
__global__ void norm_kernel(float4* __restrict__ out,
                            const float4* __restrict__ gamma4,
                            const float4* __restrict__ beta4) {
    const int c4 = threadIdx.x & 15;
    const int ty = threadIdx.x >> 4;
    const int g  = c4 >> 1;
    const float m   = g_mean[g];
    const float inv = g_inv[g];
    float4 ga = __ldg(gamma4 + c4);
    float4 be = __ldg(beta4  + c4);
    ga.x *= inv; ga.y *= inv; ga.z *= inv; ga.w *= inv;
    be.x -= m * ga.x; be.y -= m * ga.y; be.z -= m * ga.z; be.w -= m * ga.w;
#pragma unroll 4
    for (int row = blockIdx.x * 16 + ty; row < NPTS; row += gridDim.x * 16) {
        float4 v = out[row * 16 + c4];
        v.x = fmaf(v.x, ga.x, be.x); v.x = (v.x >= 0.f) ? v.x : 0.01f * v.x;
        v.y = fmaf(v.y, ga.y, be.y); v.y = (v.y >= 0.f) ? v.y : 0.01f * v.y;
        v.z = fmaf(v.z, ga.z, be.z); v.z = (v.z >= 0.f) ? v.z : 0.01f * v.z;
        v.w = fmaf(v.w, ga.w, be.w); v.w = (v.w >= 0.f) ? v.w : 0.01f * v.w;
        out[row * 16 + c4] = v;
    }
}

extern "C" void kernel_launch(void* const* d_in, const int* in_sizes, int n_in,
                              void* d_out, int out_size) {
    const float* feats   = (const float*)d_in[0];
    const float* weight  = (const float*)d_in[1];
    const float* gamma   = (const float*)d_in[2];
    const float* beta    = (const float*)d_in[3];
    const void*  in_idx  = d_in[4];
    const void*  out_idx = d_in[5];
    float* out = (float*)d_out;

    detect_kernel<<<1, 256>>>((const unsigned int*)in_idx);

    const int n4 = NPTS * COUT / 4;
    zero_kernel<<<(n4 + 255) / 256, 256>>>((float4*)out, n4);

    dim3 cgrid((NPAIRS + 255) / 256, KOFF);   // 391 x 27 blocks, 8 warps each
    conv_kernel<<<cgrid, 256>>>(feats, weight, in_idx, out_idx, out);

    stats_kernel<<<1184, 256>>>((const float4*)out);
    finalize_kernel<<<1, 32>>>();
    norm_kernel<<<2048, 256>>>((float4*)out, (const float4*)gamma, (const float4*)beta);
}

// round 7
// speedup vs baseline: 1.7987x; 1.7987x over previous
#include <cuda_runtime.h>

#define NPTS   300000
#define NPAIRS 100000
#define KOFF   27
#define CIN    32
#define COUT   64
#define NGRP   8

// ---- scratch (no allocations allowed) ----
__device__ float g_sum[NGRP];
__device__ float g_sq[NGRP];
__device__ float g_mean[NGRP];
__device__ float g_inv[NGRP];
__device__ int   g_is64;

// ---- packed fp32x2 helpers (sm_100+) ----
__device__ __forceinline__ unsigned long long pack2(float lo, float hi) {
    unsigned long long r;
    asm("mov.b64 %0, {%1, %2};" : "=l"(r) : "f"(lo), "f"(hi));
    return r;
}
__device__ __forceinline__ float hadd2(unsigned long long v) {
    float lo, hi;
    asm("mov.b64 {%0, %1}, %2;" : "=f"(lo), "=f"(hi) : "l"(v));
    return lo + hi;
}
#define FMA2(acc, b, w) \
    asm("fma.rn.f32x2 %0, %1, %2, %0;" : "+l"(acc) : "l"(b), "l"(w))

__device__ __forceinline__ void red_add_v2(float* addr, float x, float y) {
    asm volatile("red.global.add.v2.f32 [%0], {%1, %2};"
                 :: "l"(addr), "f"(x), "f"(y) : "memory");
}

// Detect whether index arrays are int64 or int32 (jax x64 flag ambiguity).
__global__ void detect_kernel(const unsigned int* __restrict__ idx32) {
    __shared__ int s_any;
    if (threadIdx.x == 0) s_any = 0;
    __syncthreads();
    unsigned int v = 0;
    for (int i = threadIdx.x; i < 2048; i += blockDim.x)
        v |= idx32[2 * i + 1];
    if (v) atomicOr(&s_any, 1);
    __syncthreads();
    if (threadIdx.x == 0) g_is64 = (s_any == 0) ? 1 : 0;
}

__global__ void zero_kernel(float4* __restrict__ out, int n4) {
    int i = blockIdx.x * blockDim.x + threadIdx.x;
    if (i < n4) out[i] = make_float4(0.f, 0.f, 0.f, 0.f);
    if (blockIdx.x == 0 && threadIdx.x < NGRP) {
        g_sum[threadIdx.x] = 0.f;
        g_sq[threadIdx.x]  = 0.f;
    }
}

__device__ __forceinline__ int load_idx(const void* p, long long pos, int is64) {
    if (is64) return (int)((const long long*)p)[pos];
    return ((const int*)p)[pos];
}

// Sparse conv: one warp per batch of 32 pairs.
// LOAD PHASE (once per warp): 8 coalesced LDG.128 — lane l fetches 16B of
// row 4g+(l>>3), chunk l&7 — staging all 32 feature rows (4 KB) into smem.
// COMPUTE PHASE: per pair, 8 broadcast LDS.128 feed fma.rn.f32x2 pairs
// directly (lane owns channels 2l, 2l+1); scatter via red.global.add.v2.f32.
__global__ __launch_bounds__(256, 2)
void conv_kernel(const float* __restrict__ feats,
                 const float* __restrict__ weight,
                 const void*  __restrict__ in_idx,
                 const void*  __restrict__ out_idx,
                 float*       __restrict__ out) {
    const int k    = blockIdx.y;
    const int lane = threadIdx.x & 31;
    const int warp = threadIdx.x >> 5;

    __shared__ float      ws[CIN * COUT];
    __shared__ ulonglong2 stage[8][32 * 8];   // 8 warps x (32 rows x 8 chunks of 16B)

    const float* wk = weight + (long long)k * CIN * COUT;
    for (int i = threadIdx.x; i < CIN * COUT; i += blockDim.x) ws[i] = wk[i];
    __syncthreads();

    // wp0[c2] = (W[2c2][2l], W[2c2+1][2l]) ; wp1 same for channel 2l+1
    unsigned long long wp0[16], wp1[16];
#pragma unroll
    for (int c2 = 0; c2 < 16; c2++) {
        wp0[c2] = pack2(ws[(2*c2) * COUT + 2*lane],     ws[(2*c2+1) * COUT + 2*lane]);
        wp1[c2] = pack2(ws[(2*c2) * COUT + 2*lane + 1], ws[(2*c2+1) * COUT + 2*lane + 1]);
    }

    const int is64 = g_is64;
    const long long base = (long long)k * NPAIRS;
    const int p0 = (blockIdx.x * 8 + warp) * 32;
    if (p0 >= NPAIRS) return;           // NPAIRS % 32 == 0: active warps are full

    const int p = p0 + lane;
    int ir   = load_idx(in_idx,  base + p, is64);
    int orow = load_idx(out_idx, base + p, is64);

    // ---- load phase: 8 LDG.128, 4 rows each ----
    ulonglong2* st = stage[warp];
    const int sub = lane >> 3;          // which of 4 rows in this group
    const int q   = lane & 7;           // 16B chunk within row
#pragma unroll
    for (int g = 0; g < 8; g++) {
        const int r    = 4 * g + sub;
        const int irow = __shfl_sync(0xffffffffu, ir, r);
        ulonglong2 v = __ldg((const ulonglong2*)(feats + (long long)irow * CIN) + q);
        st[r * 8 + q] = v;
    }
    __syncwarp();

    // ---- compute phase ----
    for (int j = 0; j < 32; j++) {
        const int ro = __shfl_sync(0xffffffffu, orow, j);
        const ulonglong2* rowp = st + j * 8;
        unsigned long long a0 = 0ull, a1 = 0ull;
#pragma unroll
        for (int c = 0; c < 8; c++) {
            ulonglong2 fv = rowp[c];    // broadcast LDS.128
            FMA2(a0, fv.x, wp0[2*c]);   FMA2(a1, fv.x, wp1[2*c]);
            FMA2(a0, fv.y, wp0[2*c+1]); FMA2(a1, fv.y, wp1[2*c+1]);
        }
        red_add_v2(out + (long long)ro * COUT + 2*lane, hadd2(a0), hadd2(a1));
    }
}

// GroupNorm stats: float4 loads; 4 channels per thread all lie in one group.
__global__ void stats_kernel(const float4* __restrict__ out) {
    const int c4   = threadIdx.x & 15;
    const int ty   = threadIdx.x >> 4;
    const int lane = threadIdx.x & 31;
    __shared__ float s_sum[NGRP], s_sq[NGRP];
    if (threadIdx.x < NGRP) { s_sum[threadIdx.x] = 0.f; s_sq[threadIdx.x] = 0.f; }
    __syncthreads();

    float sum = 0.f, sq = 0.f;
#pragma unroll 4
    for (int row = blockIdx.x * 16 + ty; row < NPTS; row += gridDim.x * 16) {
        float4 v = __ldg(out + row * 16 + c4);
        sum += (v.x + v.y) + (v.z + v.w);
        sq   = fmaf(v.x, v.x, fmaf(v.y, v.y, fmaf(v.z, v.z, fmaf(v.w, v.w, sq))));
    }
    sum += __shfl_xor_sync(0xffffffffu, sum, 16);
    sq  += __shfl_xor_sync(0xffffffffu, sq,  16);
    sum += __shfl_xor_sync(0xffffffffu, sum, 1);
    sq  += __shfl_xor_sync(0xffffffffu, sq,  1);
    if (lane < 16 && !(lane & 1)) {
        atomicAdd(&s_sum[lane >> 1], sum);
        atomicAdd(&s_sq[lane >> 1],  sq);
    }
    __syncthreads();
    if (threadIdx.x < NGRP) {
        atomicAdd(&g_sum[threadIdx.x], s_sum[threadIdx.x]);
        atomicAdd(&g_sq[threadIdx.x],  s_sq[threadIdx.x]);
    }
}

__global__ void finalize_kernel() {
    int g = threadIdx.x;
    if (g < NGRP) {
        const float cnt = (float)NPTS * (COUT / NGRP);
        float m   = g_sum[g] / cnt;
        float var = g_sq[g] / cnt - m * m;
        g_mean[g] = m;
        g_inv[g]  = rsqrtf(var + 1e-5f);
    }
}

// Fused affine + LeakyReLU, float4 in/out.
__global__ void norm_kernel(float4* __restrict__ out,
                            const float4* __restrict__ gamma4,
                            const float4* __restrict__ beta4) {
    const int c4 = threadIdx.x & 15;
    const int ty = threadIdx.x >> 4;
    const int g  = c4 >> 1;
    const float m   = g_mean[g];
    const float inv = g_inv[g];
    float4 ga = __ldg(gamma4 + c4);
    float4 be = __ldg(beta4  + c4);
    ga.x *= inv; ga.y *= inv; ga.z *= inv; ga.w *= inv;
    be.x -= m * ga.x; be.y -= m * ga.y; be.z -= m * ga.z; be.w -= m * ga.w;
#pragma unroll 4
    for (int row = blockIdx.x * 16 + ty; row < NPTS; row += gridDim.x * 16) {
        float4 v = out[row * 16 + c4];
        v.x = fmaf(v.x, ga.x, be.x); v.x = (v.x >= 0.f) ? v.x : 0.01f * v.x;
        v.y = fmaf(v.y, ga.y, be.y); v.y = (v.y >= 0.f) ? v.y : 0.01f * v.y;
        v.z = fmaf(v.z, ga.z, be.z); v.z = (v.z >= 0.f) ? v.z : 0.01f * v.z;
        v.w = fmaf(v.w, ga.w, be.w); v.w = (v.w >= 0.f) ? v.w : 0.01f * v.w;
        out[row * 16 + c4] = v;
    }
}

extern "C" void kernel_launch(void* const* d_in, const int* in_sizes, int n_in,
                              void* d_out, int out_size) {
    const float* feats   = (const float*)d_in[0];
    const float* weight  = (const float*)d_in[1];
    const float* gamma   = (const float*)d_in[2];
    const float* beta    = (const float*)d_in[3];
    const void*  in_idx  = d_in[4];
    const void*  out_idx = d_in[5];
    float* out = (float*)d_out;

    detect_kernel<<<1, 256>>>((const unsigned int*)in_idx);

    const int n4 = NPTS * COUT / 4;
    zero_kernel<<<(n4 + 255) / 256, 256>>>((float4*)out, n4);

    dim3 cgrid((NPAIRS + 255) / 256, KOFF);   // 391 x 27 blocks, 8 warps each
    conv_kernel<<<cgrid, 256>>>(feats, weight, in_idx, out_idx, out);

    stats_kernel<<<1184, 256>>>((const float4*)out);
    finalize_kernel<<<1, 32>>>();
    norm_kernel<<<2048, 256>>>((float4*)out, (const float4*)gamma, (const float4*)beta);
}